// round 1
// baseline (speedup 1.0000x reference)
#include <cuda_runtime.h>

#define P_ASEM 0.8f

// Scratch for per-row scores: s_i (includes +bias) and s_j.
// Max expected rows = B*N = 16384; pad generously (still only 512 KB).
__device__ float g_si[65536];
__device__ float g_sj[65536];

// ---------------------------------------------------------------------------
// Kernel 1: per-row dual dot product.
//   si[r] = dot(x[r,:], W[0:D]) + b
//   sj[r] = dot(x[r,:], W[D:2D])
// One warp per row; each lane consumes 4 floats (float4), D=128 -> 32 lanes x 4.
// ---------------------------------------------------------------------------
__global__ void row_scores_kernel(const float4* __restrict__ x4,
                                  const float4* __restrict__ W4,
                                  const float* __restrict__ bptr,
                                  int n_rows, int d4 /* = D/4 = 32 */)
{
    int warp_id = (blockIdx.x * blockDim.x + threadIdx.x) >> 5;
    int lane = threadIdx.x & 31;
    if (warp_id >= n_rows) return;

    float s1 = 0.f, s2 = 0.f;
    // d4 == 32 for D=128: exactly one float4 per lane.
    if (lane < d4) {
        float4 xv = x4[warp_id * d4 + lane];
        float4 w1 = W4[lane];        // W[0:D]
        float4 w2 = W4[d4 + lane];   // W[D:2D]
        s1 = xv.x * w1.x + xv.y * w1.y + xv.z * w1.z + xv.w * w1.w;
        s2 = xv.x * w2.x + xv.y * w2.y + xv.z * w2.z + xv.w * w2.w;
    }
    #pragma unroll
    for (int off = 16; off > 0; off >>= 1) {
        s1 += __shfl_down_sync(0xFFFFFFFFu, s1, off);
        s2 += __shfl_down_sync(0xFFFFFFFFu, s2, off);
    }
    if (lane == 0) {
        g_si[warp_id] = s1 + *bptr;  // fold bias into si
        g_sj[warp_id] = s2;
    }
}

// ---------------------------------------------------------------------------
// Kernel 2: fused elementwise pass (HBM-bound).
//   out[b,i,j] = P*sigmoid(si[b,i] + sj[b,j]) + (1-P)*adj[b,i,j]
// float4 over j. log2(N/4)=9, log2(N)=11 passed for address math.
// ---------------------------------------------------------------------------
__global__ void __launch_bounds__(256)
fuse_kernel(const float4* __restrict__ adj4,
            float4* __restrict__ out4,
            int total4, int log2_n4, int log2_n)
{
    int e = blockIdx.x * blockDim.x + threadIdx.x;
    if (e >= total4) return;

    int row = e >> log2_n4;          // flat (b*N + i)
    int j4  = e & ((1 << log2_n4) - 1);
    int b   = row >> log2_n;

    float  si = g_si[row];
    float4 sj = reinterpret_cast<const float4*>(g_sj)[(b << log2_n4) + j4];
    float4 a  = adj4[e];

    float4 r;
    {
        float z;
        z = si + sj.x; r.x = P_ASEM * __fdividef(1.f, 1.f + __expf(-z)) + (1.f - P_ASEM) * a.x;
        z = si + sj.y; r.y = P_ASEM * __fdividef(1.f, 1.f + __expf(-z)) + (1.f - P_ASEM) * a.y;
        z = si + sj.z; r.z = P_ASEM * __fdividef(1.f, 1.f + __expf(-z)) + (1.f - P_ASEM) * a.z;
        z = si + sj.w; r.w = P_ASEM * __fdividef(1.f, 1.f + __expf(-z)) + (1.f - P_ASEM) * a.w;
    }
    out4[e] = r;
}

extern "C" void kernel_launch(void* const* d_in, const int* in_sizes, int n_in,
                              void* d_out, int out_size)
{
    const float* x   = (const float*)d_in[0];   // [B, N, D]
    const float* adj = (const float*)d_in[1];   // [B, N, N]
    const float* W   = (const float*)d_in[2];   // [2D]
    const float* b   = (const float*)d_in[3];   // scalar

    const int D = 128;
    int n_rows = in_sizes[0] / D;               // B*N = 16384
    // N from adj: in_sizes[1] = B*N*N, in_sizes[0] = B*N*D
    long long N_ll = (long long)in_sizes[1] * D / in_sizes[0];
    int N = (int)N_ll;                           // 2048
    // log2 helpers (N is a power of two here: 2048)
    int log2_n = 0; while ((1 << log2_n) < N) log2_n++;
    int log2_n4 = log2_n - 2;

    // Kernel 1: one warp per row, 256 threads/block -> 8 rows/block
    {
        int warps_per_block = 8;
        int blocks = (n_rows + warps_per_block - 1) / warps_per_block;
        row_scores_kernel<<<blocks, 256>>>(
            (const float4*)x, (const float4*)W, b, n_rows, D / 4);
    }

    // Kernel 2: fused elementwise over out_size elements (float4)
    {
        int total4 = out_size / 4;               // 8.39M
        int threads = 256;
        int blocks = (total4 + threads - 1) / threads;
        fuse_kernel<<<blocks, threads>>>(
            (const float4*)adj, (float4*)d_out, total4, log2_n4, log2_n);
    }
}

// round 2
// speedup vs baseline: 1.0437x; 1.0437x over previous
#include <cuda_runtime.h>

#define P_ASEM 0.8f

// Scratch for per-row scores: s_i (includes +bias) and s_j.
__device__ float g_si[65536];
__device__ float g_sj[65536];

// ---------------------------------------------------------------------------
// Kernel 1: per-row dual dot product (warp per row, coalesced float4).
// ---------------------------------------------------------------------------
__global__ void row_scores_kernel(const float4* __restrict__ x4,
                                  const float4* __restrict__ W4,
                                  const float* __restrict__ bptr,
                                  int n_rows, int d4 /* = D/4 = 32 */)
{
    int warp_id = (blockIdx.x * blockDim.x + threadIdx.x) >> 5;
    int lane = threadIdx.x & 31;
    if (warp_id >= n_rows) return;

    float s1 = 0.f, s2 = 0.f;
    if (lane < d4) {
        float4 xv = __ldg(x4 + warp_id * d4 + lane);
        float4 w1 = __ldg(W4 + lane);        // W[0:D]
        float4 w2 = __ldg(W4 + d4 + lane);   // W[D:2D]
        s1 = xv.x * w1.x + xv.y * w1.y + xv.z * w1.z + xv.w * w1.w;
        s2 = xv.x * w2.x + xv.y * w2.y + xv.z * w2.z + xv.w * w2.w;
    }
    #pragma unroll
    for (int off = 16; off > 0; off >>= 1) {
        s1 += __shfl_down_sync(0xFFFFFFFFu, s1, off);
        s2 += __shfl_down_sync(0xFFFFFFFFu, s2, off);
    }
    if (lane == 0) {
        g_si[warp_id] = s1 + *bptr;  // fold bias into si
        g_sj[warp_id] = s2;
    }
}

// ---------------------------------------------------------------------------
// Kernel 2: fused elementwise pass, 4 float4 per thread, loads front-batched
// for MLP=4. Streaming hints: adj/out touched once; sj gather L1-resident.
// ---------------------------------------------------------------------------
#define VEC 4

__device__ __forceinline__ float4 sigfuse(float si, float4 sj, float4 a)
{
    float4 r; float z;
    z = si + sj.x; r.x = P_ASEM * __fdividef(1.f, 1.f + __expf(-z)) + (1.f - P_ASEM) * a.x;
    z = si + sj.y; r.y = P_ASEM * __fdividef(1.f, 1.f + __expf(-z)) + (1.f - P_ASEM) * a.y;
    z = si + sj.z; r.z = P_ASEM * __fdividef(1.f, 1.f + __expf(-z)) + (1.f - P_ASEM) * a.z;
    z = si + sj.w; r.w = P_ASEM * __fdividef(1.f, 1.f + __expf(-z)) + (1.f - P_ASEM) * a.w;
    return r;
}

__global__ void __launch_bounds__(256)
fuse_kernel(const float4* __restrict__ adj4,
            float4* __restrict__ out4,
            int total4, int log2_n4, int log2_n)
{
    const float4* __restrict__ sj4 = reinterpret_cast<const float4*>(g_sj);
    int base = blockIdx.x * (256 * VEC) + threadIdx.x;

    if (base + 3 * 256 < total4) {
        // Fast path: all 4 in range. Front-batch the 4 adj loads (MLP=4).
        int e0 = base, e1 = base + 256, e2 = base + 512, e3 = base + 768;
        float4 a0 = __ldcs(adj4 + e0);
        float4 a1 = __ldcs(adj4 + e1);
        float4 a2 = __ldcs(adj4 + e2);
        float4 a3 = __ldcs(adj4 + e3);

        int mask = (1 << log2_n4) - 1;
        int r0 = e0 >> log2_n4, r1 = e1 >> log2_n4, r2 = e2 >> log2_n4, r3 = e3 >> log2_n4;
        float si0 = g_si[r0], si1 = g_si[r1], si2 = g_si[r2], si3 = g_si[r3];
        float4 s0 = __ldg(sj4 + ((r0 >> log2_n) << log2_n4) + (e0 & mask));
        float4 s1 = __ldg(sj4 + ((r1 >> log2_n) << log2_n4) + (e1 & mask));
        float4 s2 = __ldg(sj4 + ((r2 >> log2_n) << log2_n4) + (e2 & mask));
        float4 s3 = __ldg(sj4 + ((r3 >> log2_n) << log2_n4) + (e3 & mask));

        __stcs(out4 + e0, sigfuse(si0, s0, a0));
        __stcs(out4 + e1, sigfuse(si1, s1, a1));
        __stcs(out4 + e2, sigfuse(si2, s2, a2));
        __stcs(out4 + e3, sigfuse(si3, s3, a3));
    } else {
        // Tail path (only last block, if any).
        int mask = (1 << log2_n4) - 1;
        #pragma unroll
        for (int k = 0; k < VEC; k++) {
            int e = base + k * 256;
            if (e < total4) {
                float4 a = __ldcs(adj4 + e);
                int row = e >> log2_n4;
                float si = g_si[row];
                float4 sj = __ldg(sj4 + ((row >> log2_n) << log2_n4) + (e & mask));
                __stcs(out4 + e, sigfuse(si, sj, a));
            }
        }
    }
}

extern "C" void kernel_launch(void* const* d_in, const int* in_sizes, int n_in,
                              void* d_out, int out_size)
{
    const float* x   = (const float*)d_in[0];   // [B, N, D]
    const float* adj = (const float*)d_in[1];   // [B, N, N]
    const float* W   = (const float*)d_in[2];   // [2D]
    const float* b   = (const float*)d_in[3];   // scalar

    const int D = 128;
    int n_rows = in_sizes[0] / D;               // B*N = 16384
    long long N_ll = (long long)in_sizes[1] * D / in_sizes[0];
    int N = (int)N_ll;                           // 2048
    int log2_n = 0; while ((1 << log2_n) < N) log2_n++;
    int log2_n4 = log2_n - 2;

    // Kernel 1: one warp per row.
    {
        int warps_per_block = 8;
        int blocks = (n_rows + warps_per_block - 1) / warps_per_block;
        row_scores_kernel<<<blocks, 256>>>(
            (const float4*)x, (const float4*)W, b, n_rows, D / 4);
    }

    // Kernel 2: 4 float4 per thread.
    {
        int total4 = out_size / 4;               // 8.39M
        int per_block = 256 * VEC;
        int blocks = (total4 + per_block - 1) / per_block;
        fuse_kernel<<<blocks, 256>>>(
            (const float4*)adj, (float4*)d_out, total4, log2_n4, log2_n);
    }
}

// round 3
// speedup vs baseline: 1.0515x; 1.0075x over previous
#include <cuda_runtime.h>

// Scratch for per-row scores: s_i (includes +bias) and s_j.
__device__ float g_si[65536];
__device__ float g_sj[65536];

// ---------------------------------------------------------------------------
// Kernel 1 (primary): per-row dual dot product (warp per row).
// Triggers programmatic launch of the fuse kernel at CTA start so the fuse
// kernel's independent adj loads overlap this kernel's execution.
// ---------------------------------------------------------------------------
__global__ void row_scores_kernel(const float4* __restrict__ x4,
                                  const float4* __restrict__ W4,
                                  const float* __restrict__ bptr,
                                  int n_rows, int d4 /* = D/4 = 32 */)
{
    asm volatile("griddepcontrol.launch_dependents;" ::: "memory");

    int warp_id = (blockIdx.x * blockDim.x + threadIdx.x) >> 5;
    int lane = threadIdx.x & 31;
    if (warp_id >= n_rows) return;

    float s1 = 0.f, s2 = 0.f;
    if (lane < d4) {
        float4 xv = __ldg(x4 + warp_id * d4 + lane);
        float4 w1 = __ldg(W4 + lane);        // W[0:D]
        float4 w2 = __ldg(W4 + d4 + lane);   // W[D:2D]
        s1 = xv.x * w1.x + xv.y * w1.y + xv.z * w1.z + xv.w * w1.w;
        s2 = xv.x * w2.x + xv.y * w2.y + xv.z * w2.z + xv.w * w2.w;
    }
    #pragma unroll
    for (int off = 16; off > 0; off >>= 1) {
        s1 += __shfl_down_sync(0xFFFFFFFFu, s1, off);
        s2 += __shfl_down_sync(0xFFFFFFFFu, s2, off);
    }
    if (lane == 0) {
        g_si[warp_id] = s1 + *bptr;  // fold bias into si
        g_sj[warp_id] = s2;
    }
}

// ---------------------------------------------------------------------------
// Kernel 2 (secondary): fused elementwise pass.
//   out = 0.4*tanh((si+sj)/2) + 0.4 + 0.2*adj     [== 0.8*sigmoid + 0.2*adj]
// 4 float4 per thread, adj loads front-batched BEFORE griddepcontrol.wait.
// ---------------------------------------------------------------------------
#define VEC 4

__device__ __forceinline__ float sigterm(float z, float a)
{
    // 0.8*sigmoid(z) + 0.2*a = 0.4*tanh(0.5*z) + 0.4 + 0.2*a
    float t;
    asm("tanh.approx.f32 %0, %1;" : "=f"(t) : "f"(z * 0.5f));
    return fmaf(0.4f, t, fmaf(0.2f, a, 0.4f));
}

__device__ __forceinline__ float4 sigfuse(float si, float4 sj, float4 a)
{
    float4 r;
    r.x = sigterm(si + sj.x, a.x);
    r.y = sigterm(si + sj.y, a.y);
    r.z = sigterm(si + sj.z, a.z);
    r.w = sigterm(si + sj.w, a.w);
    return r;
}

__global__ void __launch_bounds__(256)
fuse_kernel(const float4* __restrict__ adj4,
            float4* __restrict__ out4,
            int total4, int log2_n4, int log2_n)
{
    const float4* __restrict__ sj4 = reinterpret_cast<const float4*>(g_sj);
    int base = blockIdx.x * (256 * VEC) + threadIdx.x;

    if (base + 3 * 256 < total4) {
        int e0 = base, e1 = base + 256, e2 = base + 512, e3 = base + 768;
        // Independent DRAM loads issued before the grid-dependency wait:
        // they overlap the primary kernel's execution under PDL.
        float4 a0 = __ldcs(adj4 + e0);
        float4 a1 = __ldcs(adj4 + e1);
        float4 a2 = __ldcs(adj4 + e2);
        float4 a3 = __ldcs(adj4 + e3);

        asm volatile("griddepcontrol.wait;" ::: "memory");

        int mask = (1 << log2_n4) - 1;
        int r0 = e0 >> log2_n4, r1 = e1 >> log2_n4, r2 = e2 >> log2_n4, r3 = e3 >> log2_n4;
        float si0 = g_si[r0], si1 = g_si[r1], si2 = g_si[r2], si3 = g_si[r3];
        float4 s0 = __ldg(sj4 + ((r0 >> log2_n) << log2_n4) + (e0 & mask));
        float4 s1 = __ldg(sj4 + ((r1 >> log2_n) << log2_n4) + (e1 & mask));
        float4 s2 = __ldg(sj4 + ((r2 >> log2_n) << log2_n4) + (e2 & mask));
        float4 s3 = __ldg(sj4 + ((r3 >> log2_n) << log2_n4) + (e3 & mask));

        __stcs(out4 + e0, sigfuse(si0, s0, a0));
        __stcs(out4 + e1, sigfuse(si1, s1, a1));
        __stcs(out4 + e2, sigfuse(si2, s2, a2));
        __stcs(out4 + e3, sigfuse(si3, s3, a3));
    } else {
        asm volatile("griddepcontrol.wait;" ::: "memory");
        int mask = (1 << log2_n4) - 1;
        #pragma unroll
        for (int k = 0; k < VEC; k++) {
            int e = base + k * 256;
            if (e < total4) {
                float4 a = __ldcs(adj4 + e);
                int row = e >> log2_n4;
                float si = g_si[row];
                float4 sj = __ldg(sj4 + ((row >> log2_n) << log2_n4) + (e & mask));
                __stcs(out4 + e, sigfuse(si, sj, a));
            }
        }
    }
}

extern "C" void kernel_launch(void* const* d_in, const int* in_sizes, int n_in,
                              void* d_out, int out_size)
{
    const float* x   = (const float*)d_in[0];   // [B, N, D]
    const float* adj = (const float*)d_in[1];   // [B, N, N]
    const float* W   = (const float*)d_in[2];   // [2D]
    const float* b   = (const float*)d_in[3];   // scalar

    const int D = 128;
    int n_rows = in_sizes[0] / D;               // B*N = 16384
    long long N_ll = (long long)in_sizes[1] * D / in_sizes[0];
    int N = (int)N_ll;                           // 2048
    int log2_n = 0; while ((1 << log2_n) < N) log2_n++;
    int log2_n4 = log2_n - 2;

    // Kernel 1 (primary).
    {
        int warps_per_block = 8;
        int blocks = (n_rows + warps_per_block - 1) / warps_per_block;
        row_scores_kernel<<<blocks, 256>>>(
            (const float4*)x, (const float4*)W, b, n_rows, D / 4);
    }

    // Kernel 2 (secondary) with programmatic dependent launch.
    {
        int total4 = out_size / 4;               // 8.39M
        int per_block = 256 * VEC;
        int blocks = (total4 + per_block - 1) / per_block;

        cudaLaunchAttribute attrs[1];
        attrs[0].id = cudaLaunchAttributeProgrammaticStreamSerialization;
        attrs[0].val.programmaticStreamSerializationAllowed = 1;

        cudaLaunchConfig_t cfg = {};
        cfg.gridDim = dim3((unsigned)blocks, 1, 1);
        cfg.blockDim = dim3(256, 1, 1);
        cfg.dynamicSmemBytes = 0;
        cfg.stream = 0;
        cfg.attrs = attrs;
        cfg.numAttrs = 1;

        cudaError_t err = cudaLaunchKernelEx(&cfg, fuse_kernel,
            (const float4*)adj, (float4*)d_out, total4, log2_n4, log2_n);
        if (err != cudaSuccess) {
            // Fallback: plain launch (griddepcontrol.wait is a no-op without PDL).
            cudaGetLastError();
            fuse_kernel<<<blocks, 256>>>(
                (const float4*)adj, (float4*)d_out, total4, log2_n4, log2_n);
        }
    }
}